// round 2
// baseline (speedup 1.0000x reference)
#include <cuda_runtime.h>
#include <math.h>

#define N_NODES 500000
#define N_EDGES 3000000

// Scratch: layer-1 aggregated (and relu-clamped via init-0) node features [N,16]
__device__ float g_h1[N_NODES * 16];

// ---------------------------------------------------------------------------
// Kernel 0: init. g_h1 <- 0 (relu-clamp built into max), d_out <- -inf.
// ---------------------------------------------------------------------------
__global__ void init_kernel(float4* __restrict__ out4) {
    int i = blockIdx.x * blockDim.x + threadIdx.x;
    int stride = gridDim.x * blockDim.x;
    float4* a = (float4*)g_h1;
    const float4 z = make_float4(0.f, 0.f, 0.f, 0.f);
    for (int j = i; j < N_NODES * 4; j += stride) a[j] = z;
    const float NI = __int_as_float(0xFF800000);  // -inf
    const float4 ni = make_float4(NI, NI, NI, NI);
    for (int j = i; j < N_NODES; j += stride) out4[j] = ni;
}

// float atomic-max via signed/unsigned bit trick (exact, order-independent)
__device__ __forceinline__ void atomic_max_float(float* addr, float v) {
    if (v >= 0.f) atomicMax((int*)addr, __float_as_int(v));
    else          atomicMin((unsigned int*)addr, __float_as_uint(v));
}

// ---------------------------------------------------------------------------
// Kernel 1: EdgeConv layer 1.  x[N,3] -> scatter-max into g_h1[N,16].
// h = relu([x_i, x_j-x_i] @ w1a + b1a) @ w1b + b1b ; g_h1[dst] = max(g_h1[dst], h)
// Accumulator starts at 0, so values <= 0 never matter -> skip those atomics.
// Additionally: read-before-RED — accumulator only grows, so v <= cur is a
// race-safe skip that turns most REDs into plain L2 loads.
// ---------------------------------------------------------------------------
__global__ void __launch_bounds__(256) edge1_kernel(
    const float* __restrict__ x, const int* __restrict__ ei,
    const float* __restrict__ w1a, const float* __restrict__ b1a,
    const float* __restrict__ w1b, const float* __restrict__ b1b) {
    __shared__ float sw1a[96], sb1a[16], sw1b[256], sb1b[16];
    int t = threadIdx.x;
    if (t < 96)  sw1a[t] = w1a[t];
    if (t < 16)  { sb1a[t] = b1a[t]; sb1b[t] = b1b[t]; }
    sw1b[t] = w1b[t];                   // blockDim == 256
    __syncthreads();

    int e = blockIdx.x * 256 + t;
    if (e >= N_EDGES) return;
    int s = ei[e];
    int d = ei[N_EDGES + e];

    float xi0 = __ldg(&x[3 * d]),     xi1 = __ldg(&x[3 * d + 1]), xi2 = __ldg(&x[3 * d + 2]);
    float dj0 = __ldg(&x[3 * s])     - xi0;
    float dj1 = __ldg(&x[3 * s + 1]) - xi1;
    float dj2 = __ldg(&x[3 * s + 2]) - xi2;
    float in6[6] = {xi0, xi1, xi2, dj0, dj1, dj2};

    float hid[16];
#pragma unroll
    for (int k = 0; k < 16; k++) {
        float a = sb1a[k];
#pragma unroll
        for (int c = 0; c < 6; c++) a = fmaf(in6[c], sw1a[c * 16 + k], a);
        hid[k] = fmaxf(a, 0.f);
    }

    float* dstp = g_h1 + (long long)d * 16;
#pragma unroll
    for (int k = 0; k < 16; k++) {
        float a = sb1b[k];
#pragma unroll
        for (int j = 0; j < 16; j++) a = fmaf(hid[j], sw1b[j * 16 + k], a);
        if (a > 0.f) {  // accumulator init is 0: non-positive values can't win
            // read-before-RED: cur only grows; skip if we can't win
            float cur = *((volatile float*)(dstp + k));
            if (a > cur)
                atomicMax((int*)(dstp + k), __float_as_int(a));
        }
    }
}

// ---------------------------------------------------------------------------
// Kernel 2: EdgeConv layer 2.  g_h1[N,16] -> scatter-max into out[N,4] (-inf init).
// ---------------------------------------------------------------------------
__global__ void __launch_bounds__(256) edge2_kernel(
    const int* __restrict__ ei,
    const float* __restrict__ w2a, const float* __restrict__ b2a,
    const float* __restrict__ w2b, const float* __restrict__ b2b,
    float* __restrict__ out) {
    __shared__ float sw2a[128], sb2a[4], sw2b[16], sb2b[4];
    int t = threadIdx.x;
    if (t < 128) sw2a[t] = w2a[t];
    if (t < 16)  sw2b[t] = w2b[t];
    if (t < 4)   { sb2a[t] = b2a[t]; sb2b[t] = b2b[t]; }
    __syncthreads();

    int e = blockIdx.x * 256 + t;
    if (e >= N_EDGES) return;
    int s = ei[e];
    int d = ei[N_EDGES + e];

    const float4* hip = (const float4*)(g_h1 + (long long)d * 16);
    const float4* hjp = (const float4*)(g_h1 + (long long)s * 16);
    float hi[16], hj[16];
#pragma unroll
    for (int q = 0; q < 4; q++) {
        float4 a = __ldg(&hip[q]);
        float4 b = __ldg(&hjp[q]);
        hi[4 * q] = a.x; hi[4 * q + 1] = a.y; hi[4 * q + 2] = a.z; hi[4 * q + 3] = a.w;
        hj[4 * q] = b.x; hj[4 * q + 1] = b.y; hj[4 * q + 2] = b.z; hj[4 * q + 3] = b.w;
    }

    float hid[4];
#pragma unroll
    for (int k = 0; k < 4; k++) {
        float a = sb2a[k];
#pragma unroll
        for (int c = 0; c < 16; c++) a = fmaf(hi[c], sw2a[c * 4 + k], a);
#pragma unroll
        for (int c = 0; c < 16; c++) a = fmaf(hj[c] - hi[c], sw2a[(16 + c) * 4 + k], a);
        hid[k] = fmaxf(a, 0.f);
    }

    float* dstp = out + (long long)d * 4;
#pragma unroll
    for (int k = 0; k < 4; k++) {
        float a = sb2b[k];
#pragma unroll
        for (int j = 0; j < 4; j++) a = fmaf(hid[j], sw2b[j * 4 + k], a);
        // read-before-RED: monotone accumulator, skip if we can't win.
        // (-inf compares correctly; no NaNs are produced here.)
        float cur = *((volatile float*)(dstp + k));
        if (!(a <= cur))
            atomic_max_float(dstp + k, a);
    }
}

// ---------------------------------------------------------------------------
// Kernel 3: finalize.  -inf -> 0, then log_softmax over the 4 channels.
// ---------------------------------------------------------------------------
__global__ void __launch_bounds__(256) finalize_kernel(float4* __restrict__ out4) {
    int i = blockIdx.x * 256 + threadIdx.x;
    if (i >= N_NODES) return;
    float4 v = out4[i];
    if (!isfinite(v.x)) v.x = 0.f;
    if (!isfinite(v.y)) v.y = 0.f;
    if (!isfinite(v.z)) v.z = 0.f;
    if (!isfinite(v.w)) v.w = 0.f;
    float m = fmaxf(fmaxf(v.x, v.y), fmaxf(v.z, v.w));
    float s = expf(v.x - m) + expf(v.y - m) + expf(v.z - m) + expf(v.w - m);
    float l = m + logf(s);
    v.x -= l; v.y -= l; v.z -= l; v.w -= l;
    out4[i] = v;
}

extern "C" void kernel_launch(void* const* d_in, const int* in_sizes, int n_in,
                              void* d_out, int out_size) {
    const float* x   = (const float*)d_in[0];
    const int*   ei  = (const int*)d_in[1];
    const float* w1a = (const float*)d_in[2];
    const float* b1a = (const float*)d_in[3];
    const float* w1b = (const float*)d_in[4];
    const float* b1b = (const float*)d_in[5];
    const float* w2a = (const float*)d_in[6];
    const float* b2a = (const float*)d_in[7];
    const float* w2b = (const float*)d_in[8];
    const float* b2b = (const float*)d_in[9];
    float* out = (float*)d_out;

    init_kernel<<<2048, 256>>>((float4*)out);
    int eb = (N_EDGES + 255) / 256;
    edge1_kernel<<<eb, 256>>>(x, ei, w1a, b1a, w1b, b1b);
    edge2_kernel<<<eb, 256>>>(ei, w2a, b2a, w2b, b2b, out);
    int nb = (N_NODES + 255) / 256;
    finalize_kernel<<<nb, 256>>>((float4*)out);
}

// round 4
// speedup vs baseline: 1.0499x; 1.0499x over previous
#include <cuda_runtime.h>
#include <cuda_fp16.h>
#include <math.h>

#define N_NODES 500000
#define N_EDGES 3000000

// Scratch buffers (device globals — no allocation allowed)
__device__ float  g_h1[N_NODES * 16];   // layer-1 fp32 accumulator (atomic target)
__device__ __half g_h1h[N_NODES * 16];  // fp16 gather copy for layer 2
__device__ float4 g_x4[N_NODES];        // padded x for single-load gathers

// ---------------------------------------------------------------------------
// Kernel 0: pack x -> float4 table, zero g_h1, set out <- -inf.
// ---------------------------------------------------------------------------
__global__ void init_kernel(const float* __restrict__ x, float4* __restrict__ out4) {
    int i = blockIdx.x * blockDim.x + threadIdx.x;
    int stride = gridDim.x * blockDim.x;
    for (int j = i; j < N_NODES; j += stride)
        g_x4[j] = make_float4(x[3 * j], x[3 * j + 1], x[3 * j + 2], 0.f);
    float4* a = (float4*)g_h1;
    const float4 z = make_float4(0.f, 0.f, 0.f, 0.f);
    for (int j = i; j < N_NODES * 4; j += stride) a[j] = z;
    const float NI = __int_as_float(0xFF800000);  // -inf
    const float4 ni = make_float4(NI, NI, NI, NI);
    for (int j = i; j < N_NODES; j += stride) out4[j] = ni;
}

// float atomic-max via signed/unsigned bit trick (exact, order-independent)
__device__ __forceinline__ void atomic_max_float(float* addr, float v) {
    if (v >= 0.f) atomicMax((int*)addr, __float_as_int(v));
    else          atomicMin((unsigned int*)addr, __float_as_uint(v));
}

// ---------------------------------------------------------------------------
// Kernel 1: EdgeConv layer 1.  g_x4 -> scatter-max into g_h1[N,16].
// One float4 gather per endpoint (was 3 scalar gathers).
// ---------------------------------------------------------------------------
__global__ void __launch_bounds__(256) edge1_kernel(
    const int* __restrict__ ei,
    const float* __restrict__ w1a, const float* __restrict__ b1a,
    const float* __restrict__ w1b, const float* __restrict__ b1b) {
    __shared__ float sw1a[96], sb1a[16], sw1b[256], sb1b[16];
    int t = threadIdx.x;
    if (t < 96)  sw1a[t] = w1a[t];
    if (t < 16)  { sb1a[t] = b1a[t]; sb1b[t] = b1b[t]; }
    sw1b[t] = w1b[t];                   // blockDim == 256
    __syncthreads();

    int e = blockIdx.x * 256 + t;
    if (e >= N_EDGES) return;
    int s = ei[e];
    int d = ei[N_EDGES + e];

    float4 xi = __ldg(&g_x4[d]);
    float4 xj = __ldg(&g_x4[s]);
    float in6[6] = {xi.x, xi.y, xi.z, xj.x - xi.x, xj.y - xi.y, xj.z - xi.z};

    float hid[16];
#pragma unroll
    for (int k = 0; k < 16; k++) {
        float a = sb1a[k];
#pragma unroll
        for (int c = 0; c < 6; c++) a = fmaf(in6[c], sw1a[c * 16 + k], a);
        hid[k] = fmaxf(a, 0.f);
    }

    float* dstp = g_h1 + (long long)d * 16;
#pragma unroll
    for (int k = 0; k < 16; k++) {
        float a = sb1b[k];
#pragma unroll
        for (int j = 0; j < 16; j++) a = fmaf(hid[j], sw1b[j * 16 + k], a);
        if (a > 0.f) {  // accumulator init is 0: non-positive values can't win
            float cur = *((volatile float*)(dstp + k));  // monotone: safe skip
            if (a > cur)
                atomicMax((int*)(dstp + k), __float_as_int(a));
        }
    }
}

// ---------------------------------------------------------------------------
// Kernel 1.5: coalesced fp32 -> fp16 conversion of h1 (halves layer-2 gather bytes)
// ---------------------------------------------------------------------------
__global__ void tohalf_kernel() {
    int i = blockIdx.x * blockDim.x + threadIdx.x;
    int stride = gridDim.x * blockDim.x;
    const float2* src = (const float2*)g_h1;
    half2* dst = (half2*)g_h1h;
    for (int j = i; j < N_NODES * 8; j += stride) {
        float2 v = src[j];
        dst[j] = __floats2half2_rn(v.x, v.y);
    }
}

__device__ __forceinline__ void unpack8(uint4 u, float* f) {
    const half2* h = (const half2*)&u;
#pragma unroll
    for (int q = 0; q < 4; q++) {
        float2 p = __half22float2(h[q]);
        f[2 * q] = p.x; f[2 * q + 1] = p.y;
    }
}

// ---------------------------------------------------------------------------
// Kernel 2: EdgeConv layer 2.  g_h1h[N,16] (fp16) -> scatter-max into out[N,4].
// 4 gather loads per edge (was 8), half the gathered bytes.
// ---------------------------------------------------------------------------
__global__ void __launch_bounds__(256) edge2_kernel(
    const int* __restrict__ ei,
    const float* __restrict__ w2a, const float* __restrict__ b2a,
    const float* __restrict__ w2b, const float* __restrict__ b2b,
    float* __restrict__ out) {
    __shared__ float sw2a[128], sb2a[4], sw2b[16], sb2b[4];
    int t = threadIdx.x;
    if (t < 128) sw2a[t] = w2a[t];
    if (t < 16)  sw2b[t] = w2b[t];
    if (t < 4)   { sb2a[t] = b2a[t]; sb2b[t] = b2b[t]; }
    __syncthreads();

    int e = blockIdx.x * 256 + t;
    if (e >= N_EDGES) return;
    int s = ei[e];
    int d = ei[N_EDGES + e];

    const uint4* hip = (const uint4*)(g_h1h + (long long)d * 16);
    uint4 a0 = __ldg(&hip[0]), a1 = __ldg(&hip[1]);
    float hi[16], hj[16];
    unpack8(a0, hi); unpack8(a1, hi + 8);

    float hid[4];
    if (s != d) {
        const uint4* hjp = (const uint4*)(g_h1h + (long long)s * 16);
        uint4 b0 = __ldg(&hjp[0]), b1 = __ldg(&hjp[1]);
        unpack8(b0, hj); unpack8(b1, hj + 8);
#pragma unroll
        for (int k = 0; k < 4; k++) {
            float a = sb2a[k];
#pragma unroll
            for (int c = 0; c < 16; c++) a = fmaf(hi[c], sw2a[c * 4 + k], a);
#pragma unroll
            for (int c = 0; c < 16; c++) a = fmaf(hj[c] - hi[c], sw2a[(16 + c) * 4 + k], a);
            hid[k] = fmaxf(a, 0.f);
        }
    } else {
        // self-loop: x_j - x_i == 0, second half of the GEMM vanishes
#pragma unroll
        for (int k = 0; k < 4; k++) {
            float a = sb2a[k];
#pragma unroll
            for (int c = 0; c < 16; c++) a = fmaf(hi[c], sw2a[c * 4 + k], a);
            hid[k] = fmaxf(a, 0.f);
        }
    }

    float* dstp = out + (long long)d * 4;
#pragma unroll
    for (int k = 0; k < 4; k++) {
        float a = sb2b[k];
#pragma unroll
        for (int j = 0; j < 4; j++) a = fmaf(hid[j], sw2b[j * 4 + k], a);
        float cur = *((volatile float*)(dstp + k));  // monotone: safe skip
        if (!(a <= cur))
            atomic_max_float(dstp + k, a);
    }
}

// ---------------------------------------------------------------------------
// Kernel 3: finalize.  -inf -> 0, then log_softmax over the 4 channels.
// ---------------------------------------------------------------------------
__global__ void __launch_bounds__(256) finalize_kernel(float4* __restrict__ out4) {
    int i = blockIdx.x * 256 + threadIdx.x;
    if (i >= N_NODES) return;
    float4 v = out4[i];
    if (!isfinite(v.x)) v.x = 0.f;
    if (!isfinite(v.y)) v.y = 0.f;
    if (!isfinite(v.z)) v.z = 0.f;
    if (!isfinite(v.w)) v.w = 0.f;
    float m = fmaxf(fmaxf(v.x, v.y), fmaxf(v.z, v.w));
    float s = expf(v.x - m) + expf(v.y - m) + expf(v.z - m) + expf(v.w - m);
    float l = m + logf(s);
    v.x -= l; v.y -= l; v.z -= l; v.w -= l;
    out4[i] = v;
}

extern "C" void kernel_launch(void* const* d_in, const int* in_sizes, int n_in,
                              void* d_out, int out_size) {
    const float* x   = (const float*)d_in[0];
    const int*   ei  = (const int*)d_in[1];
    const float* w1a = (const float*)d_in[2];
    const float* b1a = (const float*)d_in[3];
    const float* w1b = (const float*)d_in[4];
    const float* b1b = (const float*)d_in[5];
    const float* w2a = (const float*)d_in[6];
    const float* b2a = (const float*)d_in[7];
    const float* w2b = (const float*)d_in[8];
    const float* b2b = (const float*)d_in[9];
    float* out = (float*)d_out;

    init_kernel<<<2048, 256>>>(x, (float4*)out);
    int eb = (N_EDGES + 255) / 256;
    edge1_kernel<<<eb, 256>>>(ei, w1a, b1a, w1b, b1b);
    tohalf_kernel<<<2048, 256>>>();
    edge2_kernel<<<eb, 256>>>(ei, w2a, b2a, w2b, b2b, out);
    int nb = (N_NODES + 255) / 256;
    finalize_kernel<<<nb, 256>>>((float4*)out);
}

// round 6
// speedup vs baseline: 1.5138x; 1.4419x over previous
#include <cuda_runtime.h>
#include <cuda_fp16.h>
#include <math.h>

#define N_NODES 500000
#define N_EDGES 3000000

// Scratch buffers (device globals — no allocation allowed)
__device__ float  g_h1[N_NODES * 16];   // layer-1 fp32 accumulator (atomic target)
__device__ __half g_h1h[N_NODES * 16];  // fp16 gather copy for layer 2
__device__ float4 g_x4[N_NODES];        // padded x for single-load gathers

// ---------------------------------------------------------------------------
// Kernel 0: pack x -> float4 table, zero g_h1, set out <- -inf.
// ---------------------------------------------------------------------------
__global__ void init_kernel(const float* __restrict__ x, float4* __restrict__ out4) {
    int i = blockIdx.x * blockDim.x + threadIdx.x;
    int stride = gridDim.x * blockDim.x;
    for (int j = i; j < N_NODES; j += stride)
        g_x4[j] = make_float4(x[3 * j], x[3 * j + 1], x[3 * j + 2], 0.f);
    float4* a = (float4*)g_h1;
    const float4 z = make_float4(0.f, 0.f, 0.f, 0.f);
    for (int j = i; j < N_NODES * 4; j += stride) a[j] = z;
    const float NI = __int_as_float(0xFF800000);  // -inf
    const float4 ni = make_float4(NI, NI, NI, NI);
    for (int j = i; j < N_NODES; j += stride) out4[j] = ni;
}

// float atomic-max via signed/unsigned bit trick (exact, order-independent)
__device__ __forceinline__ void atomic_max_float(float* addr, float v) {
    if (v >= 0.f) atomicMax((int*)addr, __float_as_int(v));
    else          atomicMin((unsigned int*)addr, __float_as_uint(v));
}

// ---------------------------------------------------------------------------
// Kernel 1: EdgeConv layer 1.  g_x4 -> scatter-max into g_h1[N,16].
// Probe the whole accumulator row with 4 float4 loads (was 16 scalar probes);
// stale probe values are safe — atomicMax remains the correctness guard.
// ---------------------------------------------------------------------------
__global__ void __launch_bounds__(256) edge1_kernel(
    const int* __restrict__ ei,
    const float* __restrict__ w1a, const float* __restrict__ b1a,
    const float* __restrict__ w1b, const float* __restrict__ b1b) {
    __shared__ float sw1a[96], sb1a[16], sw1b[256], sb1b[16];
    int t = threadIdx.x;
    if (t < 96)  sw1a[t] = w1a[t];
    if (t < 16)  { sb1a[t] = b1a[t]; sb1b[t] = b1b[t]; }
    sw1b[t] = w1b[t];                   // blockDim == 256
    __syncthreads();

    int e = blockIdx.x * 256 + t;
    if (e >= N_EDGES) return;
    int s = ei[e];
    int d = ei[N_EDGES + e];

    float4 xi = __ldg(&g_x4[d]);
    float4 xj = __ldg(&g_x4[s]);
    float in6[6] = {xi.x, xi.y, xi.z, xj.x - xi.x, xj.y - xi.y, xj.z - xi.z};

    float hid[16];
#pragma unroll
    for (int k = 0; k < 16; k++) {
        float a = sb1a[k];
#pragma unroll
        for (int c = 0; c < 6; c++) a = fmaf(in6[c], sw1a[c * 16 + k], a);
        hid[k] = fmaxf(a, 0.f);
    }

    float outv[16];
#pragma unroll
    for (int k = 0; k < 16; k++) {
        float a = sb1b[k];
#pragma unroll
        for (int j = 0; j < 16; j++) a = fmaf(hid[j], sw1b[j * 16 + k], a);
        outv[k] = a;
    }

    // Vector probe of the current accumulator row (4 loads, not 16)
    float* dstp = g_h1 + (long long)d * 16;
    float cur[16];
#pragma unroll
    for (int q = 0; q < 4; q++) {
        float4 c = ((const float4*)dstp)[q];
        cur[4 * q] = c.x; cur[4 * q + 1] = c.y; cur[4 * q + 2] = c.z; cur[4 * q + 3] = c.w;
    }
#pragma unroll
    for (int k = 0; k < 16; k++) {
        // init 0 => non-positive can't win; stale cur => extra RED, still correct
        if (outv[k] > 0.f && outv[k] > cur[k])
            atomicMax((int*)(dstp + k), __float_as_int(outv[k]));
    }
}

// ---------------------------------------------------------------------------
// Kernel 1.5: coalesced fp32 -> fp16 conversion of h1 (halves layer-2 gather bytes)
// ---------------------------------------------------------------------------
__global__ void tohalf_kernel() {
    int i = blockIdx.x * blockDim.x + threadIdx.x;
    int stride = gridDim.x * blockDim.x;
    const float2* src = (const float2*)g_h1;
    half2* dst = (half2*)g_h1h;
    for (int j = i; j < N_NODES * 8; j += stride) {
        float2 v = src[j];
        dst[j] = __floats2half2_rn(v.x, v.y);
    }
}

__device__ __forceinline__ void unpack8(uint4 u, float* f) {
    const half2* h = (const half2*)&u;
#pragma unroll
    for (int q = 0; q < 4; q++) {
        float2 p = __half22float2(h[q]);
        f[2 * q] = p.x; f[2 * q + 1] = p.y;
    }
}

// ---------------------------------------------------------------------------
// Kernel 2: EdgeConv layer 2.  g_h1h[N,16] (fp16) -> scatter-max into out[N,4].
// Probe out row with a single float4 load (was 4 scalar probes).
// ---------------------------------------------------------------------------
__global__ void __launch_bounds__(256) edge2_kernel(
    const int* __restrict__ ei,
    const float* __restrict__ w2a, const float* __restrict__ b2a,
    const float* __restrict__ w2b, const float* __restrict__ b2b,
    float* __restrict__ out) {
    __shared__ float sw2a[128], sb2a[4], sw2b[16], sb2b[4];
    int t = threadIdx.x;
    if (t < 128) sw2a[t] = w2a[t];
    if (t < 16)  sw2b[t] = w2b[t];
    if (t < 4)   { sb2a[t] = b2a[t]; sb2b[t] = b2b[t]; }
    __syncthreads();

    int e = blockIdx.x * 256 + t;
    if (e >= N_EDGES) return;
    int s = ei[e];
    int d = ei[N_EDGES + e];

    const uint4* hip = (const uint4*)(g_h1h + (long long)d * 16);
    uint4 a0 = __ldg(&hip[0]), a1 = __ldg(&hip[1]);
    float hi[16], hj[16];
    unpack8(a0, hi); unpack8(a1, hi + 8);

    float hid[4];
    if (s != d) {
        const uint4* hjp = (const uint4*)(g_h1h + (long long)s * 16);
        uint4 b0 = __ldg(&hjp[0]), b1 = __ldg(&hjp[1]);
        unpack8(b0, hj); unpack8(b1, hj + 8);
#pragma unroll
        for (int k = 0; k < 4; k++) {
            float a = sb2a[k];
#pragma unroll
            for (int c = 0; c < 16; c++) a = fmaf(hi[c], sw2a[c * 4 + k], a);
#pragma unroll
            for (int c = 0; c < 16; c++) a = fmaf(hj[c] - hi[c], sw2a[(16 + c) * 4 + k], a);
            hid[k] = fmaxf(a, 0.f);
        }
    } else {
        // self-loop: x_j - x_i == 0, second half of the GEMM vanishes
#pragma unroll
        for (int k = 0; k < 4; k++) {
            float a = sb2a[k];
#pragma unroll
            for (int c = 0; c < 16; c++) a = fmaf(hi[c], sw2a[c * 4 + k], a);
            hid[k] = fmaxf(a, 0.f);
        }
    }

    float ov[4];
#pragma unroll
    for (int k = 0; k < 4; k++) {
        float a = sb2b[k];
#pragma unroll
        for (int j = 0; j < 4; j++) a = fmaf(hid[j], sw2b[j * 4 + k], a);
        ov[k] = a;
    }

    float* dstp = out + (long long)d * 4;
    float4 c = *((const float4*)dstp);   // single vector probe; stale-safe
    float cur[4] = {c.x, c.y, c.z, c.w};
#pragma unroll
    for (int k = 0; k < 4; k++) {
        if (!(ov[k] <= cur[k]))
            atomic_max_float(dstp + k, ov[k]);
    }
}

// ---------------------------------------------------------------------------
// Kernel 3: finalize.  -inf -> 0, then log_softmax over the 4 channels.
// ---------------------------------------------------------------------------
__global__ void __launch_bounds__(256) finalize_kernel(float4* __restrict__ out4) {
    int i = blockIdx.x * 256 + threadIdx.x;
    if (i >= N_NODES) return;
    float4 v = out4[i];
    if (!isfinite(v.x)) v.x = 0.f;
    if (!isfinite(v.y)) v.y = 0.f;
    if (!isfinite(v.z)) v.z = 0.f;
    if (!isfinite(v.w)) v.w = 0.f;
    float m = fmaxf(fmaxf(v.x, v.y), fmaxf(v.z, v.w));
    float s = expf(v.x - m) + expf(v.y - m) + expf(v.z - m) + expf(v.w - m);
    float l = m + logf(s);
    v.x -= l; v.y -= l; v.z -= l; v.w -= l;
    out4[i] = v;
}

extern "C" void kernel_launch(void* const* d_in, const int* in_sizes, int n_in,
                              void* d_out, int out_size) {
    const float* x   = (const float*)d_in[0];
    const int*   ei  = (const int*)d_in[1];
    const float* w1a = (const float*)d_in[2];
    const float* b1a = (const float*)d_in[3];
    const float* w1b = (const float*)d_in[4];
    const float* b1b = (const float*)d_in[5];
    const float* w2a = (const float*)d_in[6];
    const float* b2a = (const float*)d_in[7];
    const float* w2b = (const float*)d_in[8];
    const float* b2b = (const float*)d_in[9];
    float* out = (float*)d_out;

    init_kernel<<<2048, 256>>>(x, (float4*)out);
    int eb = (N_EDGES + 255) / 256;
    edge1_kernel<<<eb, 256>>>(ei, w1a, b1a, w1b, b1b);
    tohalf_kernel<<<2048, 256>>>();
    edge2_kernel<<<eb, 256>>>(ei, w2a, b2a, w2b, b2b, out);
    int nb = (N_NODES + 255) / 256;
    finalize_kernel<<<nb, 256>>>((float4*)out);
}